// round 9
// baseline (speedup 1.0000x reference)
#include <cuda_runtime.h>
#include <cuda_bf16.h>

typedef unsigned long long u64;

#define F_E   10
#define F_XT  5
#define F_XS  10
#define F_U   10
#define D1    15
#define D2    81
#define MAXN  100000
#define MAXE  4000000

// ---- device scratch (no allocs allowed) ------------------------------------
__device__ int g_hist[MAXN];
__device__ int g_start[MAXN];
__device__ int g_rank[MAXE];
__device__ __align__(16) float g_scratch[(size_t)MAXE * 16];   // 256MB msg rows
__device__ __align__(16) float g_stats[(size_t)MAXN * 64];     // {mu,std,skew,kurt} per (n,j)

// ---- f32x2 packed helpers ----------------------------------------------------
__device__ __forceinline__ u64 pk(float a, float b) {
    u64 r; asm("mov.b64 %0, {%1, %2};" : "=l"(r) : "f"(a), "f"(b)); return r;
}
__device__ __forceinline__ void upk(u64 v, float& a, float& b) {
    asm("mov.b64 {%0, %1}, %2;" : "=f"(a), "=f"(b) : "l"(v));
}
__device__ __forceinline__ u64 fma2(u64 a, u64 b, u64 c) {
    u64 d; asm("fma.rn.f32x2 %0, %1, %2, %3;" : "=l"(d) : "l"(a), "l"(b), "l"(c)); return d;
}

// ---- 1: zero histogram ---------------------------------------------------------
__global__ void zero_hist(int n) {
    int i = blockIdx.x * blockDim.x + threadIdx.x;
    if (i < n) g_hist[i] = 0;
}

// ---- 2: histogram + per-edge rank (old value of the atomic) ---------------------
__global__ void hist_kernel(const int* __restrict__ src, int E_) {
    long long base = ((long long)blockIdx.x * blockDim.x + threadIdx.x) * 4;
    if (base >= E_) return;
    if (base + 4 <= E_) {
        int4 s = *(const int4*)(src + base);
        int r0 = atomicAdd(&g_hist[s.x], 1);
        int r1 = atomicAdd(&g_hist[s.y], 1);
        int r2 = atomicAdd(&g_hist[s.z], 1);
        int r3 = atomicAdd(&g_hist[s.w], 1);
        *(int4*)(g_rank + base) = make_int4(r0, r1, r2, r3);
    } else {
        for (long long e = base; e < E_; e++)
            g_rank[e] = atomicAdd(&g_hist[src[e]], 1);
    }
}

// ---- 3: single-block exclusive scan over counts ---------------------------------
__global__ void scan_kernel(int n) {   // <<<1, 1024>>>
    __shared__ int ssum[1024];
    int tid = threadIdx.x;
    int per = (n + 1023) / 1024;
    int lo = tid * per;
    int hi = (lo + per < n) ? lo + per : n;
    int sum = 0;
    for (int i = lo; i < hi; i++) sum += g_hist[i];
    ssum[tid] = sum;
    __syncthreads();
#pragma unroll
    for (int off = 1; off < 1024; off <<= 1) {
        int t = (tid >= off) ? ssum[tid - off] : 0;
        __syncthreads();
        ssum[tid] += t;
        __syncthreads();
    }
    int run = ssum[tid] - sum;      // exclusive prefix for this chunk
    for (int i = lo; i < hi; i++) {
        g_start[i] = run;
        run += g_hist[i];
    }
}

// ---- 4: edge kernel: 4 edges/thread, f32x2 MLP, streaming scattered writes ------
__global__ __launch_bounds__(128) void edge_kernel(
    const float* __restrict__ x_t,
    const float* __restrict__ edge_attr,
    const int* __restrict__ eidx,
    const float* __restrict__ w1a, const float* __restrict__ b1a,
    const float* __restrict__ w2a, const float* __restrict__ b2a,
    int E_)
{
    __shared__ float2 sw1[D1 * D1];
    __shared__ float2 sw2[D1 * D1];
    __shared__ float2 sb1[D1];
    __shared__ float2 sb2[D1];
    for (int i = threadIdx.x; i < D1 * D1; i += blockDim.x) {
        float w = w1a[i]; sw1[i] = make_float2(w, w);
        w = w2a[i];       sw2[i] = make_float2(w, w);
    }
    if (threadIdx.x < D1) {
        float v = b1a[threadIdx.x]; sb1[threadIdx.x] = make_float2(v, v);
        v = b2a[threadIdx.x];       sb2[threadIdx.x] = make_float2(v, v);
    }
    __syncthreads();

    long long t = (long long)blockIdx.x * blockDim.x + threadIdx.x;
    long long base = t * 4;
    if (base >= E_) return;
    int ecnt = (int)(((long long)E_ - base) < 4 ? ((long long)E_ - base) : 4);

    int srcs[4], tgs[4], rks[4];
    if (ecnt == 4) {
        int4 s4 = *(const int4*)(eidx + base);
        int4 g4 = *(const int4*)(eidx + (size_t)E_ + base);
        int4 r4 = *(const int4*)(g_rank + base);
        srcs[0] = s4.x; srcs[1] = s4.y; srcs[2] = s4.z; srcs[3] = s4.w;
        tgs[0] = g4.x; tgs[1] = g4.y; tgs[2] = g4.z; tgs[3] = g4.w;
        rks[0] = r4.x; rks[1] = r4.y; rks[2] = r4.z; rks[3] = r4.w;
    } else {
#pragma unroll
        for (int k = 0; k < 4; k++) {
            long long e = (k < ecnt) ? base + k : base;
            srcs[k] = eidx[e];
            tgs[k] = eidx[(size_t)E_ + e];
            rks[k] = g_rank[e];
        }
    }

    // deterministic sorted slots (no atomics)
    int pos[4];
#pragma unroll
    for (int k = 0; k < 4; k++) pos[k] = __ldg(&g_start[srcs[k]]) + rks[k];

    // v0 = packed inputs for edges {0,1}, v1 = {2,3}; reused as layer-2 outputs
    u64 v0[D1], v1[D1];
#pragma unroll
    for (int c = 0; c < F_XT; c++) {
        v0[c] = pk(__ldg(x_t + (size_t)tgs[0] * F_XT + c),
                   __ldg(x_t + (size_t)tgs[1] * F_XT + c));
        v1[c] = pk(__ldg(x_t + (size_t)tgs[2] * F_XT + c),
                   __ldg(x_t + (size_t)tgs[3] * F_XT + c));
    }
    if (ecnt == 4) {
        float fl[40];
        const float4* ea = (const float4*)(edge_attr + base * F_E);
#pragma unroll
        for (int r = 0; r < 10; r++) {
            float4 q = __ldcs(ea + r);      // streaming: single use
            fl[4 * r + 0] = q.x; fl[4 * r + 1] = q.y;
            fl[4 * r + 2] = q.z; fl[4 * r + 3] = q.w;
        }
#pragma unroll
        for (int c = 0; c < F_E; c++) {
            v0[F_XT + c] = pk(fl[c], fl[10 + c]);
            v1[F_XT + c] = pk(fl[20 + c], fl[30 + c]);
        }
    } else {
#pragma unroll
        for (int c = 0; c < F_E; c++) {
            long long e0 = base, e1 = (1 < ecnt) ? base + 1 : base;
            long long e2 = (2 < ecnt) ? base + 2 : base, e3 = (3 < ecnt) ? base + 3 : base;
            v0[F_XT + c] = pk(edge_attr[e0 * F_E + c], edge_attr[e1 * F_E + c]);
            v1[F_XT + c] = pk(edge_attr[e2 * F_E + c], edge_attr[e3 * F_E + c]);
        }
    }

    const u64* W1 = (const u64*)sw1;
    const u64* W2 = (const u64*)sw2;
    const u64* B1 = (const u64*)sb1;
    const u64* B2 = (const u64*)sb2;

    u64 h0[D1], h1[D1];
#pragma unroll
    for (int j = 0; j < D1; j++) {
        u64 s0 = B1[j], s1 = s0;
#pragma unroll
        for (int i = 0; i < D1; i++) {
            u64 w = W1[i * D1 + j];
            s0 = fma2(v0[i], w, s0);
            s1 = fma2(v1[i], w, s1);
        }
        float a, b;
        upk(s0, a, b); a = fmaxf(a, 0.1f * a); b = fmaxf(b, 0.1f * b); h0[j] = pk(a, b);
        upk(s1, a, b); a = fmaxf(a, 0.1f * a); b = fmaxf(b, 0.1f * b); h1[j] = pk(a, b);
    }

    // layer 2 overwrites v0/v1 (inputs fully consumed)
#pragma unroll
    for (int j = 0; j < D1; j++) {
        u64 s0 = B2[j], s1 = s0;
#pragma unroll
        for (int i = 0; i < D1; i++) {
            u64 w = W2[i * D1 + j];
            s0 = fma2(h0[i], w, s0);
            s1 = fma2(h1[i], w, s1);
        }
        v0[j] = s0; v1[j] = s1;
    }

    // write 64B sorted rows (streaming stores, evict-first)
    {
        float a[D1], b[D1];
#pragma unroll
        for (int j = 0; j < D1; j++) upk(v0[j], a[j], b[j]);
        float4* r = (float4*)(g_scratch + (size_t)pos[0] * 16);
        if (0 < ecnt) {
            __stcs(r + 0, make_float4(a[0], a[1], a[2], a[3]));
            __stcs(r + 1, make_float4(a[4], a[5], a[6], a[7]));
            __stcs(r + 2, make_float4(a[8], a[9], a[10], a[11]));
            __stcs(r + 3, make_float4(a[12], a[13], a[14], 0.f));
        }
        r = (float4*)(g_scratch + (size_t)pos[1] * 16);
        if (1 < ecnt) {
            __stcs(r + 0, make_float4(b[0], b[1], b[2], b[3]));
            __stcs(r + 1, make_float4(b[4], b[5], b[6], b[7]));
            __stcs(r + 2, make_float4(b[8], b[9], b[10], b[11]));
            __stcs(r + 3, make_float4(b[12], b[13], b[14], 0.f));
        }
    }
    {
        float a[D1], b[D1];
#pragma unroll
        for (int j = 0; j < D1; j++) upk(v1[j], a[j], b[j]);
        float4* r = (float4*)(g_scratch + (size_t)pos[2] * 16);
        if (2 < ecnt) {
            __stcs(r + 0, make_float4(a[0], a[1], a[2], a[3]));
            __stcs(r + 1, make_float4(a[4], a[5], a[6], a[7]));
            __stcs(r + 2, make_float4(a[8], a[9], a[10], a[11]));
            __stcs(r + 3, make_float4(a[12], a[13], a[14], 0.f));
        }
        r = (float4*)(g_scratch + (size_t)pos[3] * 16);
        if (3 < ecnt) {
            __stcs(r + 0, make_float4(b[0], b[1], b[2], b[3]));
            __stcs(r + 1, make_float4(b[4], b[5], b[6], b[7]));
            __stcs(r + 2, make_float4(b[8], b[9], b[10], b[11]));
            __stcs(r + 3, make_float4(b[12], b[13], b[14], 0.f));
        }
    }
}

// ---- 5: stats kernel: one warp per node, coalesced streaming reads, 4-deep ILP --
__global__ __launch_bounds__(256) void stats_kernel(int n) {
    int warp = (blockIdx.x * blockDim.x + threadIdx.x) >> 5;
    if (warp >= n) return;
    int lane = threadIdx.x & 31;
    int j = lane & 15;
    int half = lane >> 4;

    int cnt = g_hist[warp];
    int base = g_start[warp];

    float s1 = 0.f, s2 = 0.f, s3 = 0.f, s4 = 0.f;
    float t1 = 0.f, t2 = 0.f, t3 = 0.f, t4 = 0.f;
    float u1 = 0.f, u2 = 0.f, u3 = 0.f, u4 = 0.f;
    float q1 = 0.f, q2 = 0.f, q3 = 0.f, q4 = 0.f;
    int i = half;
    for (; i + 6 < cnt; i += 8) {
        float a = __ldcs(g_scratch + (size_t)(base + i) * 16 + j);
        float b = __ldcs(g_scratch + (size_t)(base + i + 2) * 16 + j);
        float c = __ldcs(g_scratch + (size_t)(base + i + 4) * 16 + j);
        float d = __ldcs(g_scratch + (size_t)(base + i + 6) * 16 + j);
        float a2 = a * a, b2 = b * b, c2 = c * c, d2 = d * d;
        s1 += a;       t1 += b;       u1 += c;       q1 += d;
        s2 += a2;      t2 += b2;      u2 += c2;      q2 += d2;
        s3 += a2 * a;  t3 += b2 * b;  u3 += c2 * c;  q3 += d2 * d;
        s4 += a2 * a2; t4 += b2 * b2; u4 += c2 * c2; q4 += d2 * d2;
    }
    for (; i < cnt; i += 2) {
        float a = __ldcs(g_scratch + (size_t)(base + i) * 16 + j);
        float a2 = a * a;
        s1 += a; s2 += a2; s3 += a2 * a; s4 += a2 * a2;
    }
    s1 += t1 + u1 + q1;
    s2 += t2 + u2 + q2;
    s3 += t3 + u3 + q3;
    s4 += t4 + u4 + q4;

    s1 += __shfl_down_sync(0xffffffffu, s1, 16);
    s2 += __shfl_down_sync(0xffffffffu, s2, 16);
    s3 += __shfl_down_sync(0xffffffffu, s3, 16);
    s4 += __shfl_down_sync(0xffffffffu, s4, 16);

    if (lane < D1) {
        float denom = fmaxf((float)cnt, 1.f);
        float rin = 1.f / denom;
        float mu = s1 * rin, r2 = s2 * rin, r3 = s3 * rin, r4 = s4 * rin;
        float mu2 = mu * mu;
        float var = fmaxf(r2 - mu2, 0.f);
        float std_ = sqrtf(var + 1e-6f);
        float m3 = r3 - 3.f * mu * r2 + 2.f * mu * mu2;
        float m4 = r4 - 4.f * mu * r3 + 6.f * mu2 * r2 - 3.f * mu2 * mu2;
        float is = 1.f / std_;
        float is2 = is * is;
        ((float4*)g_stats)[(size_t)warp * 16 + lane] =
            make_float4(mu, std_, m3 * is2 * is, m4 * is2 * is2);
    }
}

// ---- 6: node kernel: build 81-d feature, 81->10->10 MLP -------------------------
__global__ __launch_bounds__(256) void node_kernel(
    const float* __restrict__ x_s,
    const float* __restrict__ u,
    const int* __restrict__ batch_s,
    const float* __restrict__ w1b, const float* __restrict__ b1b,
    const float* __restrict__ w2b, const float* __restrict__ b2b,
    float* __restrict__ out, int n)
{
    __shared__ float sw1[D2 * F_XS];
    __shared__ float sw2[F_XS * F_XS];
    __shared__ float sb1[F_XS];
    __shared__ float sb2[F_XS];
    for (int i = threadIdx.x; i < D2 * F_XS; i += blockDim.x) sw1[i] = w1b[i];
    for (int i = threadIdx.x; i < F_XS * F_XS; i += blockDim.x) sw2[i] = w2b[i];
    if (threadIdx.x < F_XS) {
        sb1[threadIdx.x] = b1b[threadIdx.x];
        sb2[threadIdx.x] = b2b[threadIdx.x];
    }
    __syncthreads();

    int nid = blockIdx.x * blockDim.x + threadIdx.x;
    if (nid >= n) return;

    float t[F_XS];
#pragma unroll
    for (int j = 0; j < F_XS; j++) t[j] = sb1[j];

#define ADD_FEAT(fv, i) do { \
        float _f = (fv); \
_Pragma("unroll") \
        for (int _j = 0; _j < F_XS; _j++) \
            t[_j] = fmaf(_f, sw1[(i) * F_XS + _j], t[_j]); \
    } while (0)

#pragma unroll
    for (int k = 0; k < F_XS; k++) ADD_FEAT(x_s[(size_t)nid * F_XS + k], k);

    ADD_FEAT((float)g_hist[nid], 10);

#pragma unroll
    for (int j = 0; j < D1; j++) {
        float4 st = ((const float4*)g_stats)[(size_t)nid * 16 + j];
        ADD_FEAT(st.x, 11 + j);
        ADD_FEAT(st.y, 26 + j);
        ADD_FEAT(st.z, 41 + j);
        ADD_FEAT(st.w, 56 + j);
    }

    int b = batch_s[nid];
#pragma unroll
    for (int k = 0; k < F_U; k++) ADD_FEAT(u[(size_t)b * F_U + k], 71 + k);
#undef ADD_FEAT

    float a[F_XS];
#pragma unroll
    for (int j = 0; j < F_XS; j++) a[j] = (t[j] > 0.f) ? t[j] : 0.1f * t[j];

#pragma unroll
    for (int j = 0; j < F_XS; j++) {
        float s = sb2[j];
#pragma unroll
        for (int i = 0; i < F_XS; i++) s = fmaf(a[i], sw2[i * F_XS + j], s);
        out[(size_t)nid * F_XS + j] = s;
    }
}

// ---------------------------------------------------------------------------
extern "C" void kernel_launch(void* const* d_in, const int* in_sizes, int n_in,
                              void* d_out, int out_size)
{
    const float* x_s       = (const float*)d_in[0];
    const float* x_t       = (const float*)d_in[1];
    const float* edge_attr = (const float*)d_in[2];
    const float* u         = (const float*)d_in[3];
    const int*   eidx      = (const int*)d_in[4];
    const int*   batch_s   = (const int*)d_in[5];
    const float* w1a = (const float*)d_in[6];
    const float* b1a = (const float*)d_in[7];
    const float* w2a = (const float*)d_in[8];
    const float* b2a = (const float*)d_in[9];
    const float* w1b = (const float*)d_in[10];
    const float* b1b = (const float*)d_in[11];
    const float* w2b = (const float*)d_in[12];
    const float* b2b = (const float*)d_in[13];

    int nS = in_sizes[0] / F_XS;     // 100000
    int E_ = in_sizes[2] / F_E;      // 4000000
    float* out = (float*)d_out;

    zero_hist<<<(nS + 255) / 256, 256>>>(nS);
    hist_kernel<<<(E_ / 4 + 255) / 256 + 1, 256>>>(eidx, E_);
    scan_kernel<<<1, 1024>>>(nS);
    edge_kernel<<<(E_ + 511) / 512, 128>>>(x_t, edge_attr, eidx,
                                           w1a, b1a, w2a, b2a, E_);
    stats_kernel<<<(nS * 32 + 255) / 256, 256>>>(nS);
    node_kernel<<<(nS + 255) / 256, 256>>>(x_s, u, batch_s,
                                           w1b, b1b, w2b, b2b, out, nS);
}

// round 10
// speedup vs baseline: 1.1212x; 1.1212x over previous
#include <cuda_runtime.h>
#include <cuda_bf16.h>

typedef unsigned long long u64;

#define F_E   10
#define F_XT  5
#define F_XS  10
#define F_U   10
#define D1    15
#define D2    81
#define MAXN  100000
#define MAXE  4000000

// ---- device scratch (no allocs allowed) ------------------------------------
__device__ int g_hist[MAXN];
__device__ int g_start[MAXN];
__device__ int g_rank[MAXE];
__device__ __align__(16)  float g_xtp[(size_t)MAXN * 8];        // padded x_t rows (32B)
__device__ __align__(128) float g_scratch[(size_t)MAXE * 16];   // 256MB msg rows (64B)
__device__ __align__(16)  float g_stats[(size_t)MAXN * 64];     // {mu,std,skew,kurt} per (n,j)

// ---- f32x2 packed helpers ----------------------------------------------------
__device__ __forceinline__ u64 pk(float a, float b) {
    u64 r; asm("mov.b64 %0, {%1, %2};" : "=l"(r) : "f"(a), "f"(b)); return r;
}
__device__ __forceinline__ void upk(u64 v, float& a, float& b) {
    asm("mov.b64 {%0, %1}, %2;" : "=f"(a), "=f"(b) : "l"(v));
}
__device__ __forceinline__ u64 fma2(u64 a, u64 b, u64 c) {
    u64 d; asm("fma.rn.f32x2 %0, %1, %2, %3;" : "=l"(d) : "l"(a), "l"(b), "l"(c)); return d;
}
// 256-bit streaming store (sm_100+)
__device__ __forceinline__ void st256(float* p, float a0, float a1, float a2, float a3,
                                      float a4, float a5, float a6, float a7) {
    asm volatile("st.global.cs.v8.f32 [%0], {%1,%2,%3,%4,%5,%6,%7,%8};"
        :: "l"(p), "f"(a0), "f"(a1), "f"(a2), "f"(a3),
           "f"(a4), "f"(a5), "f"(a6), "f"(a7) : "memory");
}

// ---- 1: zero histogram + pad x_t rows to 32B -----------------------------------
__global__ void prep_kernel(const float* __restrict__ x_t, int nS, int nT) {
    int i = blockIdx.x * blockDim.x + threadIdx.x;
    if (i < nS) g_hist[i] = 0;
    if (i < nT) {
        const float* p = x_t + (size_t)i * 5;
        float4* o = (float4*)(g_xtp + (size_t)i * 8);
        o[0] = make_float4(p[0], p[1], p[2], p[3]);
        o[1] = make_float4(p[4], 0.f, 0.f, 0.f);
    }
}

// ---- 2: histogram + per-edge rank (old value of the atomic) ---------------------
__global__ void hist_kernel(const int* __restrict__ src, int E_) {
    long long base = ((long long)blockIdx.x * blockDim.x + threadIdx.x) * 4;
    if (base >= E_) return;
    if (base + 4 <= E_) {
        int4 s = *(const int4*)(src + base);
        int r0 = atomicAdd(&g_hist[s.x], 1);
        int r1 = atomicAdd(&g_hist[s.y], 1);
        int r2 = atomicAdd(&g_hist[s.z], 1);
        int r3 = atomicAdd(&g_hist[s.w], 1);
        *(int4*)(g_rank + base) = make_int4(r0, r1, r2, r3);
    } else {
        for (long long e = base; e < E_; e++)
            g_rank[e] = atomicAdd(&g_hist[src[e]], 1);
    }
}

// ---- 3: single-block exclusive scan over counts ---------------------------------
__global__ void scan_kernel(int n) {   // <<<1, 1024>>>
    __shared__ int ssum[1024];
    int tid = threadIdx.x;
    int per = (n + 1023) / 1024;
    int lo = tid * per;
    int hi = (lo + per < n) ? lo + per : n;
    int sum = 0;
    for (int i = lo; i < hi; i++) sum += g_hist[i];
    ssum[tid] = sum;
    __syncthreads();
#pragma unroll
    for (int off = 1; off < 1024; off <<= 1) {
        int t = (tid >= off) ? ssum[tid - off] : 0;
        __syncthreads();
        ssum[tid] += t;
        __syncthreads();
    }
    int run = ssum[tid] - sum;
    for (int i = lo; i < hi; i++) {
        g_start[i] = run;
        run += g_hist[i];
    }
}

// ---- 4: edge kernel: 4 edges/thread, paired-LDS.128 MLP, v8 stores --------------
__global__ __launch_bounds__(128) void edge_kernel(
    const float* __restrict__ edge_attr,
    const int* __restrict__ eidx,
    const float* __restrict__ w1a, const float* __restrict__ b1a,
    const float* __restrict__ w2a, const float* __restrict__ b2a,
    int E_)
{
    // paired layout: swp[jp*15+i] = (w[i][2jp], w[i][2jp], w[i][2jp+1], w[i][2jp+1])
    __shared__ float4 swp1[120];
    __shared__ float4 swp2[120];
    __shared__ u64 sbb1[16];
    __shared__ u64 sbb2[16];
    for (int idx = threadIdx.x; idx < 120; idx += blockDim.x) {
        int jp = idx / 15, i = idx % 15;
        int j0 = 2 * jp, j1 = j0 + 1;
        float a = w1a[i * D1 + j0];
        float b = (j1 < D1) ? w1a[i * D1 + j1] : 0.f;
        swp1[idx] = make_float4(a, a, b, b);
        a = w2a[i * D1 + j0];
        b = (j1 < D1) ? w2a[i * D1 + j1] : 0.f;
        swp2[idx] = make_float4(a, a, b, b);
    }
    if (threadIdx.x < 16) {
        float v = (threadIdx.x < D1) ? b1a[threadIdx.x] : 0.f;
        sbb1[threadIdx.x] = pk(v, v);
        v = (threadIdx.x < D1) ? b2a[threadIdx.x] : 0.f;
        sbb2[threadIdx.x] = pk(v, v);
    }
    __syncthreads();

    long long t = (long long)blockIdx.x * blockDim.x + threadIdx.x;
    long long base = t * 4;
    if (base >= E_) return;
    int ecnt = (int)(((long long)E_ - base) < 4 ? ((long long)E_ - base) : 4);

    int srcs[4], tgs[4], rks[4];
    if (ecnt == 4) {
        int4 s4 = *(const int4*)(eidx + base);
        int4 g4 = *(const int4*)(eidx + (size_t)E_ + base);
        int4 r4 = *(const int4*)(g_rank + base);
        srcs[0] = s4.x; srcs[1] = s4.y; srcs[2] = s4.z; srcs[3] = s4.w;
        tgs[0] = g4.x; tgs[1] = g4.y; tgs[2] = g4.z; tgs[3] = g4.w;
        rks[0] = r4.x; rks[1] = r4.y; rks[2] = r4.z; rks[3] = r4.w;
    } else {
#pragma unroll
        for (int k = 0; k < 4; k++) {
            long long e = (k < ecnt) ? base + k : base;
            srcs[k] = eidx[e];
            tgs[k] = eidx[(size_t)E_ + e];
            rks[k] = g_rank[e];
        }
    }

    int pos[4];
#pragma unroll
    for (int k = 0; k < 4; k++) pos[k] = __ldg(&g_start[srcs[k]]) + rks[k];

    // v0 = packed inputs edges {0,1}; v1 = {2,3}; reused as layer-2 outputs
    u64 v0[D1], v1[D1];
    {
        const float4* xa = (const float4*)g_xtp;
        float4 A = __ldg(xa + 2 * (size_t)tgs[0]);
        float4 B = __ldg(xa + 2 * (size_t)tgs[1]);
        float4 C = __ldg(xa + 2 * (size_t)tgs[2]);
        float4 Dq = __ldg(xa + 2 * (size_t)tgs[3]);
        float Ax = __ldg(g_xtp + (size_t)tgs[0] * 8 + 4);
        float Bx = __ldg(g_xtp + (size_t)tgs[1] * 8 + 4);
        float Cx = __ldg(g_xtp + (size_t)tgs[2] * 8 + 4);
        float Dx = __ldg(g_xtp + (size_t)tgs[3] * 8 + 4);
        v0[0] = pk(A.x, B.x); v0[1] = pk(A.y, B.y); v0[2] = pk(A.z, B.z);
        v0[3] = pk(A.w, B.w); v0[4] = pk(Ax, Bx);
        v1[0] = pk(C.x, Dq.x); v1[1] = pk(C.y, Dq.y); v1[2] = pk(C.z, Dq.z);
        v1[3] = pk(C.w, Dq.w); v1[4] = pk(Cx, Dx);
    }
    if (ecnt == 4) {
        const float4* ea = (const float4*)(edge_attr + base * F_E);
        float4 q0 = __ldcs(ea + 0), q1 = __ldcs(ea + 1), q2 = __ldcs(ea + 2),
               q3 = __ldcs(ea + 3), q4 = __ldcs(ea + 4);
        v0[5]  = pk(q0.x, q2.z); v0[6]  = pk(q0.y, q2.w);
        v0[7]  = pk(q0.z, q3.x); v0[8]  = pk(q0.w, q3.y);
        v0[9]  = pk(q1.x, q3.z); v0[10] = pk(q1.y, q3.w);
        v0[11] = pk(q1.z, q4.x); v0[12] = pk(q1.w, q4.y);
        v0[13] = pk(q2.x, q4.z); v0[14] = pk(q2.y, q4.w);
        q0 = __ldcs(ea + 5); q1 = __ldcs(ea + 6); q2 = __ldcs(ea + 7);
        q3 = __ldcs(ea + 8); q4 = __ldcs(ea + 9);
        v1[5]  = pk(q0.x, q2.z); v1[6]  = pk(q0.y, q2.w);
        v1[7]  = pk(q0.z, q3.x); v1[8]  = pk(q0.w, q3.y);
        v1[9]  = pk(q1.x, q3.z); v1[10] = pk(q1.y, q3.w);
        v1[11] = pk(q1.z, q4.x); v1[12] = pk(q1.w, q4.y);
        v1[13] = pk(q2.x, q4.z); v1[14] = pk(q2.y, q4.w);
    } else {
#pragma unroll
        for (int c = 0; c < F_E; c++) {
            long long e0 = base, e1 = (1 < ecnt) ? base + 1 : base;
            long long e2 = (2 < ecnt) ? base + 2 : base, e3 = (3 < ecnt) ? base + 3 : base;
            v0[F_XT + c] = pk(edge_attr[e0 * F_E + c], edge_attr[e1 * F_E + c]);
            v1[F_XT + c] = pk(edge_attr[e2 * F_E + c], edge_attr[e3 * F_E + c]);
        }
    }

    // ---- layer 1: paired j, LDS.128 weight loads ----
    u64 h0[D1], h1[D1];
#pragma unroll
    for (int jp = 0; jp < 8; jp++) {
        u64 s00 = sbb1[2 * jp],     s10 = s00;
        u64 s01 = sbb1[2 * jp + 1], s11 = s01;
#pragma unroll
        for (int i = 0; i < D1; i++) {
            ulonglong2 w = *(const ulonglong2*)&swp1[jp * 15 + i];
            s00 = fma2(v0[i], w.x, s00);
            s10 = fma2(v1[i], w.x, s10);
            s01 = fma2(v0[i], w.y, s01);
            s11 = fma2(v1[i], w.y, s11);
        }
        float a, b;
        upk(s00, a, b); a = fmaxf(a, 0.1f * a); b = fmaxf(b, 0.1f * b); h0[2 * jp] = pk(a, b);
        upk(s10, a, b); a = fmaxf(a, 0.1f * a); b = fmaxf(b, 0.1f * b); h1[2 * jp] = pk(a, b);
        if (jp < 7) {
            upk(s01, a, b); a = fmaxf(a, 0.1f * a); b = fmaxf(b, 0.1f * b); h0[2 * jp + 1] = pk(a, b);
            upk(s11, a, b); a = fmaxf(a, 0.1f * a); b = fmaxf(b, 0.1f * b); h1[2 * jp + 1] = pk(a, b);
        }
    }

    // ---- layer 2: same structure, overwrites v0/v1 ----
#pragma unroll
    for (int jp = 0; jp < 8; jp++) {
        u64 s00 = sbb2[2 * jp],     s10 = s00;
        u64 s01 = sbb2[2 * jp + 1], s11 = s01;
#pragma unroll
        for (int i = 0; i < D1; i++) {
            ulonglong2 w = *(const ulonglong2*)&swp2[jp * 15 + i];
            s00 = fma2(h0[i], w.x, s00);
            s10 = fma2(h1[i], w.x, s10);
            s01 = fma2(h0[i], w.y, s01);
            s11 = fma2(h1[i], w.y, s11);
        }
        v0[2 * jp] = s00;
        v1[2 * jp] = s10;
        if (jp < 7) {
            v0[2 * jp + 1] = s01;
            v1[2 * jp + 1] = s11;
        }
    }

    // ---- stores: 2 × st.v8 per 64B row ----
    {
        float a[D1], b[D1];
#pragma unroll
        for (int j = 0; j < D1; j++) upk(v0[j], a[j], b[j]);
        float* r = g_scratch + (size_t)pos[0] * 16;
        if (0 < ecnt) {
            st256(r,     a[0], a[1], a[2],  a[3],  a[4],  a[5],  a[6],  a[7]);
            st256(r + 8, a[8], a[9], a[10], a[11], a[12], a[13], a[14], 0.f);
        }
        r = g_scratch + (size_t)pos[1] * 16;
        if (1 < ecnt) {
            st256(r,     b[0], b[1], b[2],  b[3],  b[4],  b[5],  b[6],  b[7]);
            st256(r + 8, b[8], b[9], b[10], b[11], b[12], b[13], b[14], 0.f);
        }
#pragma unroll
        for (int j = 0; j < D1; j++) upk(v1[j], a[j], b[j]);
        r = g_scratch + (size_t)pos[2] * 16;
        if (2 < ecnt) {
            st256(r,     a[0], a[1], a[2],  a[3],  a[4],  a[5],  a[6],  a[7]);
            st256(r + 8, a[8], a[9], a[10], a[11], a[12], a[13], a[14], 0.f);
        }
        r = g_scratch + (size_t)pos[3] * 16;
        if (3 < ecnt) {
            st256(r,     b[0], b[1], b[2],  b[3],  b[4],  b[5],  b[6],  b[7]);
            st256(r + 8, b[8], b[9], b[10], b[11], b[12], b[13], b[14], 0.f);
        }
    }
}

// ---- 5: stats kernel (R8-proven form: stride-4, 2 outstanding loads) ------------
__global__ __launch_bounds__(256) void stats_kernel(int n) {
    int warp = (blockIdx.x * blockDim.x + threadIdx.x) >> 5;
    if (warp >= n) return;
    int lane = threadIdx.x & 31;
    int j = lane & 15;
    int half = lane >> 4;

    int cnt = g_hist[warp];
    int base = g_start[warp];

    float s1 = 0.f, s2 = 0.f, s3 = 0.f, s4 = 0.f;
    float t1 = 0.f, t2 = 0.f, t3 = 0.f, t4 = 0.f;
    int i = half;
    for (; i + 2 < cnt; i += 4) {
        float v = __ldcs(g_scratch + (size_t)(base + i) * 16 + j);
        float w = __ldcs(g_scratch + (size_t)(base + i + 2) * 16 + j);
        float v2 = v * v, w2 = w * w;
        s1 += v;       t1 += w;
        s2 += v2;      t2 += w2;
        s3 += v2 * v;  t3 += w2 * w;
        s4 += v2 * v2; t4 += w2 * w2;
    }
    if (i < cnt) {
        float v = __ldcs(g_scratch + (size_t)(base + i) * 16 + j);
        float v2 = v * v;
        s1 += v; s2 += v2; s3 += v2 * v; s4 += v2 * v2;
    }
    s1 += t1; s2 += t2; s3 += t3; s4 += t4;

    s1 += __shfl_down_sync(0xffffffffu, s1, 16);
    s2 += __shfl_down_sync(0xffffffffu, s2, 16);
    s3 += __shfl_down_sync(0xffffffffu, s3, 16);
    s4 += __shfl_down_sync(0xffffffffu, s4, 16);

    if (lane < D1) {
        float denom = fmaxf((float)cnt, 1.f);
        float rin = 1.f / denom;
        float mu = s1 * rin, r2 = s2 * rin, r3 = s3 * rin, r4 = s4 * rin;
        float mu2 = mu * mu;
        float var = fmaxf(r2 - mu2, 0.f);
        float std_ = sqrtf(var + 1e-6f);
        float m3 = r3 - 3.f * mu * r2 + 2.f * mu * mu2;
        float m4 = r4 - 4.f * mu * r3 + 6.f * mu2 * r2 - 3.f * mu2 * mu2;
        float is = 1.f / std_;
        float is2 = is * is;
        ((float4*)g_stats)[(size_t)warp * 16 + lane] =
            make_float4(mu, std_, m3 * is2 * is, m4 * is2 * is2);
    }
}

// ---- 6: node kernel --------------------------------------------------------------
__global__ __launch_bounds__(256) void node_kernel(
    const float* __restrict__ x_s,
    const float* __restrict__ u,
    const int* __restrict__ batch_s,
    const float* __restrict__ w1b, const float* __restrict__ b1b,
    const float* __restrict__ w2b, const float* __restrict__ b2b,
    float* __restrict__ out, int n)
{
    __shared__ float sw1[D2 * F_XS];
    __shared__ float sw2[F_XS * F_XS];
    __shared__ float sb1[F_XS];
    __shared__ float sb2[F_XS];
    for (int i = threadIdx.x; i < D2 * F_XS; i += blockDim.x) sw1[i] = w1b[i];
    for (int i = threadIdx.x; i < F_XS * F_XS; i += blockDim.x) sw2[i] = w2b[i];
    if (threadIdx.x < F_XS) {
        sb1[threadIdx.x] = b1b[threadIdx.x];
        sb2[threadIdx.x] = b2b[threadIdx.x];
    }
    __syncthreads();

    int nid = blockIdx.x * blockDim.x + threadIdx.x;
    if (nid >= n) return;

    float t[F_XS];
#pragma unroll
    for (int j = 0; j < F_XS; j++) t[j] = sb1[j];

#define ADD_FEAT(fv, i) do { \
        float _f = (fv); \
_Pragma("unroll") \
        for (int _j = 0; _j < F_XS; _j++) \
            t[_j] = fmaf(_f, sw1[(i) * F_XS + _j], t[_j]); \
    } while (0)

#pragma unroll
    for (int k = 0; k < F_XS; k++) ADD_FEAT(x_s[(size_t)nid * F_XS + k], k);

    ADD_FEAT((float)g_hist[nid], 10);

#pragma unroll
    for (int j = 0; j < D1; j++) {
        float4 st = ((const float4*)g_stats)[(size_t)nid * 16 + j];
        ADD_FEAT(st.x, 11 + j);
        ADD_FEAT(st.y, 26 + j);
        ADD_FEAT(st.z, 41 + j);
        ADD_FEAT(st.w, 56 + j);
    }

    int b = batch_s[nid];
#pragma unroll
    for (int k = 0; k < F_U; k++) ADD_FEAT(u[(size_t)b * F_U + k], 71 + k);
#undef ADD_FEAT

    float a[F_XS];
#pragma unroll
    for (int j = 0; j < F_XS; j++) a[j] = (t[j] > 0.f) ? t[j] : 0.1f * t[j];

#pragma unroll
    for (int j = 0; j < F_XS; j++) {
        float s = sb2[j];
#pragma unroll
        for (int i = 0; i < F_XS; i++) s = fmaf(a[i], sw2[i * F_XS + j], s);
        out[(size_t)nid * F_XS + j] = s;
    }
}

// ---------------------------------------------------------------------------
extern "C" void kernel_launch(void* const* d_in, const int* in_sizes, int n_in,
                              void* d_out, int out_size)
{
    const float* x_s       = (const float*)d_in[0];
    const float* x_t       = (const float*)d_in[1];
    const float* edge_attr = (const float*)d_in[2];
    const float* u         = (const float*)d_in[3];
    const int*   eidx      = (const int*)d_in[4];
    const int*   batch_s   = (const int*)d_in[5];
    const float* w1a = (const float*)d_in[6];
    const float* b1a = (const float*)d_in[7];
    const float* w2a = (const float*)d_in[8];
    const float* b2a = (const float*)d_in[9];
    const float* w1b = (const float*)d_in[10];
    const float* b1b = (const float*)d_in[11];
    const float* w2b = (const float*)d_in[12];
    const float* b2b = (const float*)d_in[13];

    int nS = in_sizes[0] / F_XS;     // 100000
    int nT = in_sizes[1] / F_XT;     // 100000
    int E_ = in_sizes[2] / F_E;      // 4000000
    float* out = (float*)d_out;
    int nPrep = (nS > nT) ? nS : nT;

    prep_kernel<<<(nPrep + 255) / 256, 256>>>(x_t, nS, nT);
    hist_kernel<<<(E_ / 4 + 255) / 256 + 1, 256>>>(eidx, E_);
    scan_kernel<<<1, 1024>>>(nS);
    edge_kernel<<<(E_ + 511) / 512, 128>>>(edge_attr, eidx,
                                           w1a, b1a, w2a, b2a, E_);
    stats_kernel<<<(nS * 32 + 255) / 256, 256>>>(nS);
    node_kernel<<<(nS + 255) / 256, 256>>>(x_s, u, batch_s,
                                           w1b, b1b, w2b, b2b, out, nS);
}

// round 11
// speedup vs baseline: 1.5054x; 1.3427x over previous
#include <cuda_runtime.h>
#include <cuda_bf16.h>

typedef unsigned long long u64;

#define F_E   10
#define F_XT  5
#define F_XS  10
#define F_U   10
#define D1    15
#define D2    81
#define MAXN  100000
#define MAXE  4000000

// ---- device scratch (no allocs allowed) ------------------------------------
__device__ int g_hist[MAXN];
__device__ int g_start[MAXN];
__device__ int g_rank[MAXE];
__device__ int g_bsum[128];
__device__ __align__(16)  float g_xtp[(size_t)MAXN * 8];        // padded x_t rows (32B)
__device__ __align__(128) float g_scratch[(size_t)MAXE * 16];   // 256MB msg rows (64B)
__device__ __align__(16)  float g_stats[(size_t)MAXN * 64];     // {mu,std,skew,kurt} per (n,j)

// ---- f32x2 packed helpers ----------------------------------------------------
__device__ __forceinline__ u64 pk(float a, float b) {
    u64 r; asm("mov.b64 %0, {%1, %2};" : "=l"(r) : "f"(a), "f"(b)); return r;
}
__device__ __forceinline__ void upk(u64 v, float& a, float& b) {
    asm("mov.b64 {%0, %1}, %2;" : "=f"(a), "=f"(b) : "l"(v));
}
__device__ __forceinline__ u64 fma2(u64 a, u64 b, u64 c) {
    u64 d; asm("fma.rn.f32x2 %0, %1, %2, %3;" : "=l"(d) : "l"(a), "l"(b), "l"(c)); return d;
}
// 256-bit streaming store (sm_100+)
__device__ __forceinline__ void st256(float* p, float a0, float a1, float a2, float a3,
                                      float a4, float a5, float a6, float a7) {
    asm volatile("st.global.cs.v8.f32 [%0], {%1,%2,%3,%4,%5,%6,%7,%8};"
        :: "l"(p), "f"(a0), "f"(a1), "f"(a2), "f"(a3),
           "f"(a4), "f"(a5), "f"(a6), "f"(a7) : "memory");
}

// ---- 1: zero histogram + pad x_t rows to 32B -----------------------------------
__global__ void prep_kernel(const float* __restrict__ x_t, int nS, int nT) {
    int i = blockIdx.x * blockDim.x + threadIdx.x;
    if (i < nS) g_hist[i] = 0;
    if (i < nT) {
        const float* p = x_t + (size_t)i * 5;
        float4* o = (float4*)(g_xtp + (size_t)i * 8);
        o[0] = make_float4(p[0], p[1], p[2], p[3]);
        o[1] = make_float4(p[4], 0.f, 0.f, 0.f);
    }
}

// ---- 2: histogram + per-edge rank (old value of the atomic) ---------------------
__global__ void hist_kernel(const int* __restrict__ src, int E_) {
    long long base = ((long long)blockIdx.x * blockDim.x + threadIdx.x) * 4;
    if (base >= E_) return;
    if (base + 4 <= E_) {
        int4 s = *(const int4*)(src + base);
        int r0 = atomicAdd(&g_hist[s.x], 1);
        int r1 = atomicAdd(&g_hist[s.y], 1);
        int r2 = atomicAdd(&g_hist[s.z], 1);
        int r3 = atomicAdd(&g_hist[s.w], 1);
        *(int4*)(g_rank + base) = make_int4(r0, r1, r2, r3);
    } else {
        for (long long e = base; e < E_; e++)
            g_rank[e] = atomicAdd(&g_hist[src[e]], 1);
    }
}

// ---- 3-5: multi-block exclusive scan (R8-proven) --------------------------------
__global__ void scan1(int n) {
    __shared__ int s[1024];
    int gid = blockIdx.x * 1024 + threadIdx.x;
    int v = (gid < n) ? g_hist[gid] : 0;
    s[threadIdx.x] = v;
    __syncthreads();
#pragma unroll
    for (int off = 1; off < 1024; off <<= 1) {
        int t = (threadIdx.x >= off) ? s[threadIdx.x - off] : 0;
        __syncthreads();
        s[threadIdx.x] += t;
        __syncthreads();
    }
    int incl = s[threadIdx.x];
    if (gid < n) g_start[gid] = incl - v;
    if (threadIdx.x == 1023) g_bsum[blockIdx.x] = incl;
}

__global__ void scan2(int nb) {
    __shared__ int s[128];
    int v = (threadIdx.x < nb) ? g_bsum[threadIdx.x] : 0;
    s[threadIdx.x] = v;
    __syncthreads();
#pragma unroll
    for (int off = 1; off < 128; off <<= 1) {
        int t = (threadIdx.x >= off) ? s[threadIdx.x - off] : 0;
        __syncthreads();
        s[threadIdx.x] += t;
        __syncthreads();
    }
    if (threadIdx.x < nb) g_bsum[threadIdx.x] = s[threadIdx.x] - v;
}

__global__ void scan3(int n) {
    int gid = blockIdx.x * 1024 + threadIdx.x;
    if (gid < n) g_start[gid] += g_bsum[blockIdx.x];
}

// ---- 6: edge kernel: 4 edges/thread, paired-LDS.128 MLP, v8 stores --------------
__global__ __launch_bounds__(128) void edge_kernel(
    const float* __restrict__ edge_attr,
    const int* __restrict__ eidx,
    const float* __restrict__ w1a, const float* __restrict__ b1a,
    const float* __restrict__ w2a, const float* __restrict__ b2a,
    int E_)
{
    // paired layout: swp[jp*15+i] = (w[i][2jp], w[i][2jp], w[i][2jp+1], w[i][2jp+1])
    __shared__ float4 swp1[120];
    __shared__ float4 swp2[120];
    __shared__ u64 sbb1[16];
    __shared__ u64 sbb2[16];
    for (int idx = threadIdx.x; idx < 120; idx += blockDim.x) {
        int jp = idx / 15, i = idx % 15;
        int j0 = 2 * jp, j1 = j0 + 1;
        float a = w1a[i * D1 + j0];
        float b = (j1 < D1) ? w1a[i * D1 + j1] : 0.f;
        swp1[idx] = make_float4(a, a, b, b);
        a = w2a[i * D1 + j0];
        b = (j1 < D1) ? w2a[i * D1 + j1] : 0.f;
        swp2[idx] = make_float4(a, a, b, b);
    }
    if (threadIdx.x < 16) {
        float v = (threadIdx.x < D1) ? b1a[threadIdx.x] : 0.f;
        sbb1[threadIdx.x] = pk(v, v);
        v = (threadIdx.x < D1) ? b2a[threadIdx.x] : 0.f;
        sbb2[threadIdx.x] = pk(v, v);
    }
    __syncthreads();

    long long t = (long long)blockIdx.x * blockDim.x + threadIdx.x;
    long long base = t * 4;
    if (base >= E_) return;
    int ecnt = (int)(((long long)E_ - base) < 4 ? ((long long)E_ - base) : 4);

    int srcs[4], tgs[4], rks[4];
    if (ecnt == 4) {
        int4 s4 = *(const int4*)(eidx + base);
        int4 g4 = *(const int4*)(eidx + (size_t)E_ + base);
        int4 r4 = *(const int4*)(g_rank + base);
        srcs[0] = s4.x; srcs[1] = s4.y; srcs[2] = s4.z; srcs[3] = s4.w;
        tgs[0] = g4.x; tgs[1] = g4.y; tgs[2] = g4.z; tgs[3] = g4.w;
        rks[0] = r4.x; rks[1] = r4.y; rks[2] = r4.z; rks[3] = r4.w;
    } else {
#pragma unroll
        for (int k = 0; k < 4; k++) {
            long long e = (k < ecnt) ? base + k : base;
            srcs[k] = eidx[e];
            tgs[k] = eidx[(size_t)E_ + e];
            rks[k] = g_rank[e];
        }
    }

    int pos[4];
#pragma unroll
    for (int k = 0; k < 4; k++) pos[k] = __ldg(&g_start[srcs[k]]) + rks[k];

    // v0 = packed inputs edges {0,1}; v1 = {2,3}; reused as layer-2 outputs
    u64 v0[D1], v1[D1];
    {
        const float4* xa = (const float4*)g_xtp;
        float4 A = __ldg(xa + 2 * (size_t)tgs[0]);
        float4 B = __ldg(xa + 2 * (size_t)tgs[1]);
        float4 C = __ldg(xa + 2 * (size_t)tgs[2]);
        float4 Dq = __ldg(xa + 2 * (size_t)tgs[3]);
        float Ax = __ldg(g_xtp + (size_t)tgs[0] * 8 + 4);
        float Bx = __ldg(g_xtp + (size_t)tgs[1] * 8 + 4);
        float Cx = __ldg(g_xtp + (size_t)tgs[2] * 8 + 4);
        float Dx = __ldg(g_xtp + (size_t)tgs[3] * 8 + 4);
        v0[0] = pk(A.x, B.x); v0[1] = pk(A.y, B.y); v0[2] = pk(A.z, B.z);
        v0[3] = pk(A.w, B.w); v0[4] = pk(Ax, Bx);
        v1[0] = pk(C.x, Dq.x); v1[1] = pk(C.y, Dq.y); v1[2] = pk(C.z, Dq.z);
        v1[3] = pk(C.w, Dq.w); v1[4] = pk(Cx, Dx);
    }
    if (ecnt == 4) {
        const float4* ea = (const float4*)(edge_attr + base * F_E);
        float4 q0 = __ldcs(ea + 0), q1 = __ldcs(ea + 1), q2 = __ldcs(ea + 2),
               q3 = __ldcs(ea + 3), q4 = __ldcs(ea + 4);
        v0[5]  = pk(q0.x, q2.z); v0[6]  = pk(q0.y, q2.w);
        v0[7]  = pk(q0.z, q3.x); v0[8]  = pk(q0.w, q3.y);
        v0[9]  = pk(q1.x, q3.z); v0[10] = pk(q1.y, q3.w);
        v0[11] = pk(q1.z, q4.x); v0[12] = pk(q1.w, q4.y);
        v0[13] = pk(q2.x, q4.z); v0[14] = pk(q2.y, q4.w);
        q0 = __ldcs(ea + 5); q1 = __ldcs(ea + 6); q2 = __ldcs(ea + 7);
        q3 = __ldcs(ea + 8); q4 = __ldcs(ea + 9);
        v1[5]  = pk(q0.x, q2.z); v1[6]  = pk(q0.y, q2.w);
        v1[7]  = pk(q0.z, q3.x); v1[8]  = pk(q0.w, q3.y);
        v1[9]  = pk(q1.x, q3.z); v1[10] = pk(q1.y, q3.w);
        v1[11] = pk(q1.z, q4.x); v1[12] = pk(q1.w, q4.y);
        v1[13] = pk(q2.x, q4.z); v1[14] = pk(q2.y, q4.w);
    } else {
#pragma unroll
        for (int c = 0; c < F_E; c++) {
            long long e0 = base, e1 = (1 < ecnt) ? base + 1 : base;
            long long e2 = (2 < ecnt) ? base + 2 : base, e3 = (3 < ecnt) ? base + 3 : base;
            v0[F_XT + c] = pk(edge_attr[e0 * F_E + c], edge_attr[e1 * F_E + c]);
            v1[F_XT + c] = pk(edge_attr[e2 * F_E + c], edge_attr[e3 * F_E + c]);
        }
    }

    // ---- layer 1: paired j, LDS.128 weight loads ----
    u64 h0[D1], h1[D1];
#pragma unroll
    for (int jp = 0; jp < 8; jp++) {
        u64 s00 = sbb1[2 * jp],     s10 = s00;
        u64 s01 = sbb1[2 * jp + 1], s11 = s01;
#pragma unroll
        for (int i = 0; i < D1; i++) {
            ulonglong2 w = *(const ulonglong2*)&swp1[jp * 15 + i];
            s00 = fma2(v0[i], w.x, s00);
            s10 = fma2(v1[i], w.x, s10);
            s01 = fma2(v0[i], w.y, s01);
            s11 = fma2(v1[i], w.y, s11);
        }
        float a, b;
        upk(s00, a, b); a = fmaxf(a, 0.1f * a); b = fmaxf(b, 0.1f * b); h0[2 * jp] = pk(a, b);
        upk(s10, a, b); a = fmaxf(a, 0.1f * a); b = fmaxf(b, 0.1f * b); h1[2 * jp] = pk(a, b);
        if (jp < 7) {
            upk(s01, a, b); a = fmaxf(a, 0.1f * a); b = fmaxf(b, 0.1f * b); h0[2 * jp + 1] = pk(a, b);
            upk(s11, a, b); a = fmaxf(a, 0.1f * a); b = fmaxf(b, 0.1f * b); h1[2 * jp + 1] = pk(a, b);
        }
    }

    // ---- layer 2: same structure, overwrites v0/v1 ----
#pragma unroll
    for (int jp = 0; jp < 8; jp++) {
        u64 s00 = sbb2[2 * jp],     s10 = s00;
        u64 s01 = sbb2[2 * jp + 1], s11 = s01;
#pragma unroll
        for (int i = 0; i < D1; i++) {
            ulonglong2 w = *(const ulonglong2*)&swp2[jp * 15 + i];
            s00 = fma2(h0[i], w.x, s00);
            s10 = fma2(h1[i], w.x, s10);
            s01 = fma2(h0[i], w.y, s01);
            s11 = fma2(h1[i], w.y, s11);
        }
        v0[2 * jp] = s00;
        v1[2 * jp] = s10;
        if (jp < 7) {
            v0[2 * jp + 1] = s01;
            v1[2 * jp + 1] = s11;
        }
    }

    // ---- stores: 2 × st.v8 per 64B row ----
    {
        float a[D1], b[D1];
#pragma unroll
        for (int j = 0; j < D1; j++) upk(v0[j], a[j], b[j]);
        float* r = g_scratch + (size_t)pos[0] * 16;
        if (0 < ecnt) {
            st256(r,     a[0], a[1], a[2],  a[3],  a[4],  a[5],  a[6],  a[7]);
            st256(r + 8, a[8], a[9], a[10], a[11], a[12], a[13], a[14], 0.f);
        }
        r = g_scratch + (size_t)pos[1] * 16;
        if (1 < ecnt) {
            st256(r,     b[0], b[1], b[2],  b[3],  b[4],  b[5],  b[6],  b[7]);
            st256(r + 8, b[8], b[9], b[10], b[11], b[12], b[13], b[14], 0.f);
        }
#pragma unroll
        for (int j = 0; j < D1; j++) upk(v1[j], a[j], b[j]);
        r = g_scratch + (size_t)pos[2] * 16;
        if (2 < ecnt) {
            st256(r,     a[0], a[1], a[2],  a[3],  a[4],  a[5],  a[6],  a[7]);
            st256(r + 8, a[8], a[9], a[10], a[11], a[12], a[13], a[14], 0.f);
        }
        r = g_scratch + (size_t)pos[3] * 16;
        if (3 < ecnt) {
            st256(r,     b[0], b[1], b[2],  b[3],  b[4],  b[5],  b[6],  b[7]);
            st256(r + 8, b[8], b[9], b[10], b[11], b[12], b[13], b[14], 0.f);
        }
    }
}

// ---- 7: stats kernel (R8-proven form: stride-4, 2 outstanding loads) ------------
__global__ __launch_bounds__(256) void stats_kernel(int n) {
    int warp = (blockIdx.x * blockDim.x + threadIdx.x) >> 5;
    if (warp >= n) return;
    int lane = threadIdx.x & 31;
    int j = lane & 15;
    int half = lane >> 4;

    int cnt = g_hist[warp];
    int base = g_start[warp];

    float s1 = 0.f, s2 = 0.f, s3 = 0.f, s4 = 0.f;
    float t1 = 0.f, t2 = 0.f, t3 = 0.f, t4 = 0.f;
    int i = half;
    for (; i + 2 < cnt; i += 4) {
        float v = __ldcs(g_scratch + (size_t)(base + i) * 16 + j);
        float w = __ldcs(g_scratch + (size_t)(base + i + 2) * 16 + j);
        float v2 = v * v, w2 = w * w;
        s1 += v;       t1 += w;
        s2 += v2;      t2 += w2;
        s3 += v2 * v;  t3 += w2 * w;
        s4 += v2 * v2; t4 += w2 * w2;
    }
    if (i < cnt) {
        float v = __ldcs(g_scratch + (size_t)(base + i) * 16 + j);
        float v2 = v * v;
        s1 += v; s2 += v2; s3 += v2 * v; s4 += v2 * v2;
    }
    s1 += t1; s2 += t2; s3 += t3; s4 += t4;

    s1 += __shfl_down_sync(0xffffffffu, s1, 16);
    s2 += __shfl_down_sync(0xffffffffu, s2, 16);
    s3 += __shfl_down_sync(0xffffffffu, s3, 16);
    s4 += __shfl_down_sync(0xffffffffu, s4, 16);

    if (lane < D1) {
        float denom = fmaxf((float)cnt, 1.f);
        float rin = 1.f / denom;
        float mu = s1 * rin, r2 = s2 * rin, r3 = s3 * rin, r4 = s4 * rin;
        float mu2 = mu * mu;
        float var = fmaxf(r2 - mu2, 0.f);
        float std_ = sqrtf(var + 1e-6f);
        float m3 = r3 - 3.f * mu * r2 + 2.f * mu * mu2;
        float m4 = r4 - 4.f * mu * r3 + 6.f * mu2 * r2 - 3.f * mu2 * mu2;
        float is = 1.f / std_;
        float is2 = is * is;
        ((float4*)g_stats)[(size_t)warp * 16 + lane] =
            make_float4(mu, std_, m3 * is2 * is, m4 * is2 * is2);
    }
}

// ---- 8: node kernel --------------------------------------------------------------
__global__ __launch_bounds__(256) void node_kernel(
    const float* __restrict__ x_s,
    const float* __restrict__ u,
    const int* __restrict__ batch_s,
    const float* __restrict__ w1b, const float* __restrict__ b1b,
    const float* __restrict__ w2b, const float* __restrict__ b2b,
    float* __restrict__ out, int n)
{
    __shared__ float sw1[D2 * F_XS];
    __shared__ float sw2[F_XS * F_XS];
    __shared__ float sb1[F_XS];
    __shared__ float sb2[F_XS];
    for (int i = threadIdx.x; i < D2 * F_XS; i += blockDim.x) sw1[i] = w1b[i];
    for (int i = threadIdx.x; i < F_XS * F_XS; i += blockDim.x) sw2[i] = w2b[i];
    if (threadIdx.x < F_XS) {
        sb1[threadIdx.x] = b1b[threadIdx.x];
        sb2[threadIdx.x] = b2b[threadIdx.x];
    }
    __syncthreads();

    int nid = blockIdx.x * blockDim.x + threadIdx.x;
    if (nid >= n) return;

    float t[F_XS];
#pragma unroll
    for (int j = 0; j < F_XS; j++) t[j] = sb1[j];

#define ADD_FEAT(fv, i) do { \
        float _f = (fv); \
_Pragma("unroll") \
        for (int _j = 0; _j < F_XS; _j++) \
            t[_j] = fmaf(_f, sw1[(i) * F_XS + _j], t[_j]); \
    } while (0)

#pragma unroll
    for (int k = 0; k < F_XS; k++) ADD_FEAT(x_s[(size_t)nid * F_XS + k], k);

    ADD_FEAT((float)g_hist[nid], 10);

#pragma unroll
    for (int j = 0; j < D1; j++) {
        float4 st = ((const float4*)g_stats)[(size_t)nid * 16 + j];
        ADD_FEAT(st.x, 11 + j);
        ADD_FEAT(st.y, 26 + j);
        ADD_FEAT(st.z, 41 + j);
        ADD_FEAT(st.w, 56 + j);
    }

    int b = batch_s[nid];
#pragma unroll
    for (int k = 0; k < F_U; k++) ADD_FEAT(u[(size_t)b * F_U + k], 71 + k);
#undef ADD_FEAT

    float a[F_XS];
#pragma unroll
    for (int j = 0; j < F_XS; j++) a[j] = (t[j] > 0.f) ? t[j] : 0.1f * t[j];

#pragma unroll
    for (int j = 0; j < F_XS; j++) {
        float s = sb2[j];
#pragma unroll
        for (int i = 0; i < F_XS; i++) s = fmaf(a[i], sw2[i * F_XS + j], s);
        out[(size_t)nid * F_XS + j] = s;
    }
}

// ---------------------------------------------------------------------------
extern "C" void kernel_launch(void* const* d_in, const int* in_sizes, int n_in,
                              void* d_out, int out_size)
{
    const float* x_s       = (const float*)d_in[0];
    const float* x_t       = (const float*)d_in[1];
    const float* edge_attr = (const float*)d_in[2];
    const float* u         = (const float*)d_in[3];
    const int*   eidx      = (const int*)d_in[4];
    const int*   batch_s   = (const int*)d_in[5];
    const float* w1a = (const float*)d_in[6];
    const float* b1a = (const float*)d_in[7];
    const float* w2a = (const float*)d_in[8];
    const float* b2a = (const float*)d_in[9];
    const float* w1b = (const float*)d_in[10];
    const float* b1b = (const float*)d_in[11];
    const float* w2b = (const float*)d_in[12];
    const float* b2b = (const float*)d_in[13];

    int nS = in_sizes[0] / F_XS;     // 100000
    int nT = in_sizes[1] / F_XT;     // 100000
    int E_ = in_sizes[2] / F_E;      // 4000000
    float* out = (float*)d_out;
    int nPrep = (nS > nT) ? nS : nT;
    int nb = (nS + 1023) / 1024;     // scan blocks (<=128)

    prep_kernel<<<(nPrep + 255) / 256, 256>>>(x_t, nS, nT);
    hist_kernel<<<(E_ / 4 + 255) / 256 + 1, 256>>>(eidx, E_);
    scan1<<<nb, 1024>>>(nS);
    scan2<<<1, 128>>>(nb);
    scan3<<<nb, 1024>>>(nS);
    edge_kernel<<<(E_ + 511) / 512, 128>>>(edge_attr, eidx,
                                           w1a, b1a, w2a, b2a, E_);
    stats_kernel<<<(nS * 32 + 255) / 256, 256>>>(nS);
    node_kernel<<<(nS + 255) / 256, 256>>>(x_s, u, batch_s,
                                           w1b, b1b, w2b, b2b, out, nS);
}